// round 9
// baseline (speedup 1.0000x reference)
#include <cuda_runtime.h>
#include <cuda_bf16.h>
#include <cstdint>

typedef __nv_bfloat16 bf16;

#define NUM_EXPERTS 8
#define HIDDEN     1024
#define INTER      1024
#define M_TOK      2048
#define NSLOT      4096
#define N_GU       2048
#define MAX_TILES  40

// ---------------- device scratch ----------------
__device__ int   g_perm[NSLOT];
__device__ float g_w[NSLOT];
__device__ int4  g_work[MAX_TILES];
__device__ bf16  g_w1h[(size_t)NUM_EXPERTS * HIDDEN * N_GU];
__device__ bf16  g_w1l[(size_t)NUM_EXPERTS * HIDDEN * N_GU];
__device__ bf16  g_w2h[(size_t)NUM_EXPERTS * INTER * HIDDEN];
__device__ bf16  g_w2l[(size_t)NUM_EXPERTS * INTER * HIDDEN];
__device__ bf16  g_xh[(size_t)M_TOK * HIDDEN];
__device__ bf16  g_xl[(size_t)M_TOK * HIDDEN];
__device__ bf16  g_ih[(size_t)NSLOT * INTER];
__device__ bf16  g_il[(size_t)NSLOT * INTER];
__device__ float g_down[(size_t)NSLOT * HIDDEN];

// ---------------- routing ----------------
__global__ void route_kernel(const int* __restrict__ ridx,
                             const float* __restrict__ rw) {
    __shared__ int cnt[NUM_EXPERTS];
    __shared__ int ofs[NUM_EXPERTS];
    __shared__ int cur[NUM_EXPERTS];
    int t = threadIdx.x;
    if (t < NUM_EXPERTS) cnt[t] = 0;
    __syncthreads();
    for (int s = t; s < NSLOT; s += blockDim.x)
        atomicAdd(&cnt[ridx[s]], 1);
    __syncthreads();
    if (t == 0) {
        int acc = 0;
        for (int e = 0; e < NUM_EXPERTS; e++) { ofs[e] = acc; cur[e] = acc; acc += cnt[e]; }
    }
    __syncthreads();
    for (int s = t; s < NSLOT; s += blockDim.x) {
        int e = ridx[s];
        int p = atomicAdd(&cur[e], 1);
        g_perm[p] = s;
        g_w[p]    = rw[(s >> 1) * NUM_EXPERTS + e];
    }
    if (t == 0) {
        int n = 0;
        for (int e = 0; e < NUM_EXPERTS; e++)
            for (int r = 0; r < cnt[e]; r += 128) {
                g_work[n] = make_int4(e, ofs[e] + r, min(128, cnt[e] - r), 0);
                n++;
            }
        for (; n < MAX_TILES; n++) g_work[n] = make_int4(0, 0, 0, 0);
    }
}

// ---------------- fp32 -> bf16 (hi, lo) split ----------------
__device__ __forceinline__ void split1(float x, uint16_t& h, uint16_t& l) {
    __nv_bfloat16 xh = __float2bfloat16_rn(x);
    h = __bfloat16_as_ushort(xh);
    l = __bfloat16_as_ushort(__float2bfloat16_rn(x - __bfloat162float(xh)));
}
__device__ __forceinline__ uint32_t pack2(uint16_t a, uint16_t b) {
    return (uint32_t)a | ((uint32_t)b << 16);
}

// WHICH: 0 -> w1, 1 -> w2, 2 -> x. Destinations resolved IN DEVICE CODE.
// Each thread: 8 floats -> one uint4 store per hi/lo array (16B stores).
template<int WHICH>
__global__ void split_kernel(const float4* __restrict__ in, int n8) {
    int i = blockIdx.x * blockDim.x + threadIdx.x;
    if (i >= n8) return;
    uint4* oh; uint4* ol;
    if (WHICH == 0)      { oh = (uint4*)g_w1h; ol = (uint4*)g_w1l; }
    else if (WHICH == 1) { oh = (uint4*)g_w2h; ol = (uint4*)g_w2l; }
    else                 { oh = (uint4*)g_xh;  ol = (uint4*)g_xl;  }
    float4 v0 = in[2 * i], v1 = in[2 * i + 1];
    uint16_t h0, h1, h2, h3, h4, h5, h6, h7;
    uint16_t l0, l1, l2, l3, l4, l5, l6, l7;
    split1(v0.x, h0, l0); split1(v0.y, h1, l1);
    split1(v0.z, h2, l2); split1(v0.w, h3, l3);
    split1(v1.x, h4, l4); split1(v1.y, h5, l5);
    split1(v1.z, h6, l6); split1(v1.w, h7, l7);
    oh[i] = make_uint4(pack2(h0, h1), pack2(h2, h3), pack2(h4, h5), pack2(h6, h7));
    ol[i] = make_uint4(pack2(l0, l1), pack2(l2, l3), pack2(l4, l5), pack2(l6, l7));
}

// ---------------- MMA helpers ----------------
__device__ __forceinline__ void ldsm4(uint32_t a, uint32_t* r) {
    asm volatile("ldmatrix.sync.aligned.m8n8.x4.shared.b16 {%0,%1,%2,%3},[%4];\n"
        : "=r"(r[0]), "=r"(r[1]), "=r"(r[2]), "=r"(r[3]) : "r"(a));
}
__device__ __forceinline__ void ldsm4t(uint32_t a, uint32_t* r) {
    asm volatile("ldmatrix.sync.aligned.m8n8.x4.trans.shared.b16 {%0,%1,%2,%3},[%4];\n"
        : "=r"(r[0]), "=r"(r[1]), "=r"(r[2]), "=r"(r[3]) : "r"(a));
}
__device__ __forceinline__ void mma16816(float* c, const uint32_t* a, uint32_t b0, uint32_t b1) {
    asm volatile("mma.sync.aligned.m16n8k16.row.col.f32.bf16.bf16.f32 "
        "{%0,%1,%2,%3},{%4,%5,%6,%7},{%8,%9},{%0,%1,%2,%3};\n"
        : "+f"(c[0]), "+f"(c[1]), "+f"(c[2]), "+f"(c[3])
        : "r"(a[0]), "r"(a[1]), "r"(a[2]), "r"(a[3]), "r"(b0), "r"(b1));
}
__device__ __forceinline__ float swiglu(float g, float u) {
    g = fminf(g, 7.0f);
    u = fminf(fmaxf(u, -7.0f), 7.0f);
    return (u + 1.0f) * (g / (1.0f + __expf(-1.702f * g)));
}

#define LDA 40     // A smem stride (bf16 elems): 32 data + 8 pad
#define LDB 136    // B smem stride: 128 data + 8 pad

// dynamic smem: per stage (elems): Ah 5120 | Al 5120 | Bh 4352 | Bl 4352 = 18944
#define E_AH 0
#define E_AL 5120
#define E_BH 10240
#define E_BL 14592
#define STAGE_E 18944
#define STAGE_B (STAGE_E * 2)           // 37888 bytes
#define SMEM_BYTES (2 * STAGE_B)        // 75776 bytes

// ---------------- grouped GEMM (G1: gate_up+SwiGLU, G2: down) ----------------
template<bool G1>
__global__ void __launch_bounds__(256, 1)
gemm_kernel(const float* __restrict__ bias) {
    extern __shared__ __align__(16) uint16_t smp[];
    int4 wk = g_work[blockIdx.x];
    int rows = wk.z;
    if (rows == 0) return;
    int e = wk.x, rowStart = wk.y;
    int n0 = blockIdx.y * 128;
    const int NST = G1 ? N_GU : HIDDEN;

    int tid = threadIdx.x, lane = tid & 31, wid = tid >> 5;

    // ---- global source pointers (pre-split bf16) ----
    int arow = tid >> 1, aq = tid & 1;          // A: 2 thr/row, 16 elems each
    bool av = arow < rows;
    int r_idx = rowStart + (av ? arow : 0);
    const bf16 *aH, *aL;
    if (G1) {
        int tok = g_perm[r_idx] >> 1;
        aH = g_xh + (size_t)tok * HIDDEN + aq * 16;
        aL = g_xl + (size_t)tok * HIDDEN + aq * 16;
    } else {
        aH = g_ih + (size_t)r_idx * INTER + aq * 16;
        aL = g_il + (size_t)r_idx * INTER + aq * 16;
    }
    int bk = tid >> 3, bc = (tid & 7) * 16;     // B: 8 thr/row, 16 elems each
    const bf16* bH = (G1 ? g_w1h : g_w2h) + (size_t)e * 1024 * NST + (size_t)bk * NST + n0 + bc;
    const bf16* bL = (G1 ? g_w1l : g_w2l) + (size_t)e * 1024 * NST + (size_t)bk * NST + n0 + bc;

    uint32_t sBase = (uint32_t)__cvta_generic_to_shared(smp);

    int wm = wid & 3, wn = wid >> 2;
    int mb = wm * 32, nb = wn * 64;
    int fr = (lane & 7) + ((lane >> 3) & 1) * 8;
    int fc = (lane >> 4) * 8;

    float acc[2][8][4];
    #pragma unroll
    for (int a = 0; a < 2; a++)
        #pragma unroll
        for (int b = 0; b < 8; b++)
            #pragma unroll
            for (int c = 0; c < 4; c++) acc[a][b][c] = 0.f;

    const uint4 Z4 = make_uint4(0, 0, 0, 0);
    uint4 aRh[2], aRl[2], bRh[2], bRl[2];

    int ao = arow * LDA + aq * 16;
    int bo = bk * LDB + bc;

    auto loadRegs = [&](int k0) {
        #pragma unroll
        for (int i = 0; i < 2; i++) {
            aRh[i] = av ? *(const uint4*)(aH + k0 + 8 * i) : Z4;
            aRl[i] = av ? *(const uint4*)(aL + k0 + 8 * i) : Z4;
            bRh[i] = *(const uint4*)(bH + (size_t)k0 * NST + 8 * i);
            bRl[i] = *(const uint4*)(bL + (size_t)k0 * NST + 8 * i);
        }
    };
    auto storeStage = [&](int s) {
        uint16_t* st = smp + s * STAGE_E;
        *(uint4*)&st[E_AH + ao]     = aRh[0];
        *(uint4*)&st[E_AH + ao + 8] = aRh[1];
        *(uint4*)&st[E_AL + ao]     = aRl[0];
        *(uint4*)&st[E_AL + ao + 8] = aRl[1];
        *(uint4*)&st[E_BH + bo]     = bRh[0];
        *(uint4*)&st[E_BH + bo + 8] = bRh[1];
        *(uint4*)&st[E_BL + bo]     = bRl[0];
        *(uint4*)&st[E_BL + bo + 8] = bRl[1];
    };

    // prologue: stage 0 filled, regs hold k-block 1
    loadRegs(0);
    storeStage(0);
    __syncthreads();
    loadRegs(32);

    #pragma unroll 1
    for (int kb = 0; kb < 32; kb++) {
        if (kb + 1 < 32) storeStage((kb + 1) & 1);   // other buffer: no hazard
        if (kb + 2 < 32) loadRegs((kb + 2) * 32);

        uint32_t base = sBase + (uint32_t)(kb & 1) * STAGE_B;
        uint32_t bAh = base, bAl = base + E_AL * 2;
        uint32_t bBh = base + E_BH * 2, bBl = base + E_BL * 2;
        #pragma unroll
        for (int ks = 0; ks < 2; ks++) {
            uint32_t ah[2][4], al2[2][4];
            #pragma unroll
            for (int t2 = 0; t2 < 2; t2++) {
                uint32_t off = (uint32_t)(((mb + t2 * 16 + fr) * LDA + ks * 16 + fc) * 2);
                ldsm4(bAh + off, ah[t2]);
                ldsm4(bAl + off, al2[t2]);
            }
            #pragma unroll
            for (int p = 0; p < 4; p++) {
                uint32_t bh[4], bl2[4];
                uint32_t off = (uint32_t)(((ks * 16 + fr) * LDB + nb + p * 16 + fc) * 2);
                ldsm4t(bBh + off, bh);
                ldsm4t(bBl + off, bl2);
                #pragma unroll
                for (int t2 = 0; t2 < 2; t2++) {
                    mma16816(acc[t2][2 * p],     ah[t2],  bh[0],  bh[1]);
                    mma16816(acc[t2][2 * p],     ah[t2],  bl2[0], bl2[1]);
                    mma16816(acc[t2][2 * p],     al2[t2], bh[0],  bh[1]);
                    mma16816(acc[t2][2 * p + 1], ah[t2],  bh[2],  bh[3]);
                    mma16816(acc[t2][2 * p + 1], ah[t2],  bl2[2], bl2[3]);
                    mma16816(acc[t2][2 * p + 1], al2[t2], bh[2],  bh[3]);
                }
            }
        }
        __syncthreads();
    }

    // ---- epilogue ----
    int r4 = lane >> 2, c2 = (lane & 3) * 2;
    if (G1) {
        const float* bp = bias + e * N_GU + n0;
        #pragma unroll
        for (int t2 = 0; t2 < 2; t2++) {
            int lr0 = mb + t2 * 16 + r4;
            int lr1 = lr0 + 8;
            bool v0 = lr0 < rows, v1 = lr1 < rows;
            size_t o0 = v0 ? (size_t)(rowStart + lr0) * INTER : 0;
            size_t o1 = v1 ? (size_t)(rowStart + lr1) * INTER : 0;
            #pragma unroll
            for (int p = 0; p < 4; p++)
                #pragma unroll
                for (int nt = 0; nt < 2; nt++) {
                    int nloc = nb + p * 16 + nt * 8 + c2;
                    float2 bb = *(const float2*)(bp + nloc);
                    float* c = acc[t2][2 * p + nt];
                    int ic = (n0 + nloc) >> 1;
                    if (v0) {
                        float v = swiglu(c[0] + bb.x, c[1] + bb.y);
                        uint16_t h, l; split1(v, h, l);
                        *(uint16_t*)&g_ih[o0 + ic] = h;
                        *(uint16_t*)&g_il[o0 + ic] = l;
                    }
                    if (v1) {
                        float v = swiglu(c[2] + bb.x, c[3] + bb.y);
                        uint16_t h, l; split1(v, h, l);
                        *(uint16_t*)&g_ih[o1 + ic] = h;
                        *(uint16_t*)&g_il[o1 + ic] = l;
                    }
                }
        }
    } else {
        const float* bp = bias + e * HIDDEN + n0;
        #pragma unroll
        for (int t2 = 0; t2 < 2; t2++) {
            int lr0 = mb + t2 * 16 + r4;
            int lr1 = lr0 + 8;
            bool v0 = lr0 < rows, v1 = lr1 < rows;
            int s0 = 0, s1 = 0; float w0 = 0.f, w1 = 0.f;
            if (v0) { int r = rowStart + lr0; s0 = g_perm[r]; w0 = g_w[r]; }
            if (v1) { int r = rowStart + lr1; s1 = g_perm[r]; w1 = g_w[r]; }
            #pragma unroll
            for (int p = 0; p < 4; p++)
                #pragma unroll
                for (int nt = 0; nt < 2; nt++) {
                    int nloc = nb + p * 16 + nt * 8 + c2;
                    float2 bb = *(const float2*)(bp + nloc);
                    float* c = acc[t2][2 * p + nt];
                    if (v0) {
                        float2 v = make_float2((c[0] + bb.x) * w0, (c[1] + bb.y) * w0);
                        *(float2*)(g_down + (size_t)s0 * HIDDEN + n0 + nloc) = v;
                    }
                    if (v1) {
                        float2 v = make_float2((c[2] + bb.x) * w1, (c[3] + bb.y) * w1);
                        *(float2*)(g_down + (size_t)s1 * HIDDEN + n0 + nloc) = v;
                    }
                }
        }
    }
}

// ---------------- deterministic top-2 combine ------------------------------
__global__ void combine_kernel(float* __restrict__ out) {
    int i = blockIdx.x * blockDim.x + threadIdx.x;
    const float4* d = (const float4*)g_down;
    int tok = i >> 8;
    int c   = i & 255;
    float4 a = d[(size_t)(tok * 2)     * 256 + c];
    float4 b = d[(size_t)(tok * 2 + 1) * 256 + c];
    float4 r;
    r.x = a.x + b.x; r.y = a.y + b.y; r.z = a.z + b.z; r.w = a.w + b.w;
    ((float4*)out)[i] = r;
}

// ---------------- launch ---------------------------------------------------
extern "C" void kernel_launch(void* const* d_in, const int* in_sizes, int n_in,
                              void* d_out, int out_size) {
    const float* hs   = (const float*)d_in[0];
    const int*   ridx = (const int*)  d_in[1];
    const float* rw   = (const float*)d_in[2];
    const float* gup  = (const float*)d_in[3];
    const float* gupb = (const float*)d_in[4];
    const float* dwn  = (const float*)d_in[5];
    const float* dwnb = (const float*)d_in[6];
    float* out = (float*)d_out;

    cudaFuncSetAttribute(gemm_kernel<true>,  cudaFuncAttributeMaxDynamicSharedMemorySize, SMEM_BYTES);
    cudaFuncSetAttribute(gemm_kernel<false>, cudaFuncAttributeMaxDynamicSharedMemorySize, SMEM_BYTES);

    route_kernel<<<1, 256>>>(ridx, rw);

    // pre-split fp32 -> bf16 hi/lo (destinations bound inside device code)
    {
        int n8 = NUM_EXPERTS * HIDDEN * N_GU / 8;
        split_kernel<0><<<n8 / 256, 256>>>((const float4*)gup, n8);
    }
    {
        int n8 = NUM_EXPERTS * INTER * HIDDEN / 8;
        split_kernel<1><<<n8 / 256, 256>>>((const float4*)dwn, n8);
    }
    {
        int n8 = M_TOK * HIDDEN / 8;
        split_kernel<2><<<n8 / 256, 256>>>((const float4*)hs, n8);
    }

    dim3 grid1(MAX_TILES, N_GU / 128);    // (40, 16)
    gemm_kernel<true><<<grid1, 256, SMEM_BYTES>>>(gupb);
    dim3 grid2(MAX_TILES, HIDDEN / 128);  // (40, 8)
    gemm_kernel<false><<<grid2, 256, SMEM_BYTES>>>(dwnb);

    combine_kernel<<<M_TOK * (HIDDEN / 4) / 256, 256>>>(out);
}

// round 10
// speedup vs baseline: 1.0141x; 1.0141x over previous
#include <cuda_runtime.h>
#include <cuda_bf16.h>
#include <cstdint>

typedef __nv_bfloat16 bf16;

#define NUM_EXPERTS 8
#define HIDDEN     1024
#define INTER      1024
#define M_TOK      2048
#define NSLOT      4096
#define N_GU       2048
#define MAX_TILES  40

// ---------------- device scratch ----------------
__device__ int   g_perm[NSLOT];
__device__ float g_w[NSLOT];
__device__ int4  g_work[MAX_TILES];
__device__ bf16  g_w1h[(size_t)NUM_EXPERTS * HIDDEN * N_GU];
__device__ bf16  g_w1l[(size_t)NUM_EXPERTS * HIDDEN * N_GU];
__device__ bf16  g_w2h[(size_t)NUM_EXPERTS * INTER * HIDDEN];
__device__ bf16  g_w2l[(size_t)NUM_EXPERTS * INTER * HIDDEN];
__device__ bf16  g_xh[(size_t)M_TOK * HIDDEN];
__device__ bf16  g_xl[(size_t)M_TOK * HIDDEN];
__device__ bf16  g_ih[(size_t)NSLOT * INTER];
__device__ bf16  g_il[(size_t)NSLOT * INTER];

// ---------------- routing ----------------
__global__ void route_kernel(const int* __restrict__ ridx,
                             const float* __restrict__ rw) {
    __shared__ int cnt[NUM_EXPERTS];
    __shared__ int ofs[NUM_EXPERTS];
    __shared__ int cur[NUM_EXPERTS];
    int t = threadIdx.x;
    if (t < NUM_EXPERTS) cnt[t] = 0;
    __syncthreads();
    for (int s = t; s < NSLOT; s += blockDim.x)
        atomicAdd(&cnt[ridx[s]], 1);
    __syncthreads();
    if (t == 0) {
        int acc = 0;
        for (int e = 0; e < NUM_EXPERTS; e++) { ofs[e] = acc; cur[e] = acc; acc += cnt[e]; }
    }
    __syncthreads();
    for (int s = t; s < NSLOT; s += blockDim.x) {
        int e = ridx[s];
        int p = atomicAdd(&cur[e], 1);
        g_perm[p] = s;
        g_w[p]    = rw[(s >> 1) * NUM_EXPERTS + e];
    }
    if (t == 0) {
        int n = 0;
        for (int e = 0; e < NUM_EXPERTS; e++)
            for (int r = 0; r < cnt[e]; r += 128) {
                g_work[n] = make_int4(e, ofs[e] + r, min(128, cnt[e] - r), 0);
                n++;
            }
        for (; n < MAX_TILES; n++) g_work[n] = make_int4(0, 0, 0, 0);
    }
}

// ---------------- fp32 -> bf16 (hi, lo) split ----------------
__device__ __forceinline__ void split1(float x, uint16_t& h, uint16_t& l) {
    __nv_bfloat16 xh = __float2bfloat16_rn(x);
    h = __bfloat16_as_ushort(xh);
    l = __bfloat16_as_ushort(__float2bfloat16_rn(x - __bfloat162float(xh)));
}
__device__ __forceinline__ uint32_t pack2(uint16_t a, uint16_t b) {
    return (uint32_t)a | ((uint32_t)b << 16);
}

// WHICH: 0 -> w1, 1 -> w2, 2 -> x. Destinations bound in device code.
// Each thread: 16 floats (4x float4 loads, MLP=4) -> 2 uint4 stores per array.
template<int WHICH>
__global__ void split_kernel(const float4* __restrict__ in, int n16) {
    int i = blockIdx.x * blockDim.x + threadIdx.x;
    if (i >= n16) return;
    uint4* oh; uint4* ol;
    if (WHICH == 0)      { oh = (uint4*)g_w1h; ol = (uint4*)g_w1l; }
    else if (WHICH == 1) { oh = (uint4*)g_w2h; ol = (uint4*)g_w2l; }
    else                 { oh = (uint4*)g_xh;  ol = (uint4*)g_xl;  }
    float4 v[4];
    #pragma unroll
    for (int j = 0; j < 4; j++) v[j] = in[4 * i + j];
    #pragma unroll
    for (int half = 0; half < 2; half++) {
        uint16_t h0, h1, h2, h3, h4, h5, h6, h7;
        uint16_t l0, l1, l2, l3, l4, l5, l6, l7;
        float4 a = v[2 * half], b = v[2 * half + 1];
        split1(a.x, h0, l0); split1(a.y, h1, l1);
        split1(a.z, h2, l2); split1(a.w, h3, l3);
        split1(b.x, h4, l4); split1(b.y, h5, l5);
        split1(b.z, h6, l6); split1(b.w, h7, l7);
        oh[2 * i + half] = make_uint4(pack2(h0, h1), pack2(h2, h3), pack2(h4, h5), pack2(h6, h7));
        ol[2 * i + half] = make_uint4(pack2(l0, l1), pack2(l2, l3), pack2(l4, l5), pack2(l6, l7));
    }
}

// ---------------- MMA helpers ----------------
__device__ __forceinline__ void ldsm4(uint32_t a, uint32_t* r) {
    asm volatile("ldmatrix.sync.aligned.m8n8.x4.shared.b16 {%0,%1,%2,%3},[%4];\n"
        : "=r"(r[0]), "=r"(r[1]), "=r"(r[2]), "=r"(r[3]) : "r"(a));
}
__device__ __forceinline__ void ldsm4t(uint32_t a, uint32_t* r) {
    asm volatile("ldmatrix.sync.aligned.m8n8.x4.trans.shared.b16 {%0,%1,%2,%3},[%4];\n"
        : "=r"(r[0]), "=r"(r[1]), "=r"(r[2]), "=r"(r[3]) : "r"(a));
}
__device__ __forceinline__ void mma16816(float* c, const uint32_t* a, uint32_t b0, uint32_t b1) {
    asm volatile("mma.sync.aligned.m16n8k16.row.col.f32.bf16.bf16.f32 "
        "{%0,%1,%2,%3},{%4,%5,%6,%7},{%8,%9},{%0,%1,%2,%3};\n"
        : "+f"(c[0]), "+f"(c[1]), "+f"(c[2]), "+f"(c[3])
        : "r"(a[0]), "r"(a[1]), "r"(a[2]), "r"(a[3]), "r"(b0), "r"(b1));
}
__device__ __forceinline__ float swiglu(float g, float u) {
    g = fminf(g, 7.0f);
    u = fminf(fmaxf(u, -7.0f), 7.0f);
    return (u + 1.0f) * (g / (1.0f + __expf(-1.702f * g)));
}

#define LDA 40     // A smem stride (bf16 elems): 32 data + 8 pad
#define LDB 136    // B smem stride: 128 data + 8 pad

// ---------------- grouped GEMM (G1: gate_up+SwiGLU, G2: down+atomic combine) -
// Mainloop structure is the PROVEN R6 version (334.5us): static smem,
// register prefetch, two barriers per 32-K block. Do not reorder.
template<bool G1>
__global__ void __launch_bounds__(256, 1)
gemm_kernel(const float* __restrict__ bias, float* __restrict__ out) {
    int4 wk = g_work[blockIdx.x];
    int rows = wk.z;
    if (rows == 0) return;
    int e = wk.x, rowStart = wk.y;
    int n0 = blockIdx.y * 128;
    const int NST = G1 ? N_GU : HIDDEN;

    __shared__ uint16_t Ah[128 * LDA], Al[128 * LDA];
    __shared__ uint16_t Bh[32 * LDB],  Bl[32 * LDB];

    int tid = threadIdx.x, lane = tid & 31, wid = tid >> 5;

    // ---- global source pointers (pre-split bf16) ----
    int arow = tid >> 1, aq = tid & 1;          // A: 2 thr/row, 16 elems each
    bool av = arow < rows;
    int r_idx = rowStart + (av ? arow : 0);
    const bf16 *aH, *aL;
    if (G1) {
        int tok = g_perm[r_idx] >> 1;
        aH = g_xh + (size_t)tok * HIDDEN + aq * 16;
        aL = g_xl + (size_t)tok * HIDDEN + aq * 16;
    } else {
        aH = g_ih + (size_t)r_idx * INTER + aq * 16;
        aL = g_il + (size_t)r_idx * INTER + aq * 16;
    }
    int bk = tid >> 3, bc = (tid & 7) * 16;     // B: 8 thr/row, 16 elems each
    const bf16* bH = (G1 ? g_w1h : g_w2h) + (size_t)e * 1024 * NST + (size_t)bk * NST + n0 + bc;
    const bf16* bL = (G1 ? g_w1l : g_w2l) + (size_t)e * 1024 * NST + (size_t)bk * NST + n0 + bc;

    uint32_t sAh = (uint32_t)__cvta_generic_to_shared(Ah);
    uint32_t sAl = (uint32_t)__cvta_generic_to_shared(Al);
    uint32_t sBh = (uint32_t)__cvta_generic_to_shared(Bh);
    uint32_t sBl = (uint32_t)__cvta_generic_to_shared(Bl);

    int wm = wid & 3, wn = wid >> 2;
    int mb = wm * 32, nb = wn * 64;
    int fr = (lane & 7) + ((lane >> 3) & 1) * 8;
    int fc = (lane >> 4) * 8;

    float acc[2][8][4];
    #pragma unroll
    for (int a = 0; a < 2; a++)
        #pragma unroll
        for (int b = 0; b < 8; b++)
            #pragma unroll
            for (int c = 0; c < 4; c++) acc[a][b][c] = 0.f;

    const uint4 Z4 = make_uint4(0, 0, 0, 0);
    uint4 aRh[2], aRl[2], bRh[2], bRl[2];
    #pragma unroll
    for (int i = 0; i < 2; i++) {
        aRh[i] = av ? *(const uint4*)(aH + 8 * i) : Z4;
        aRl[i] = av ? *(const uint4*)(aL + 8 * i) : Z4;
        bRh[i] = *(const uint4*)(bH + 8 * i);
        bRl[i] = *(const uint4*)(bL + 8 * i);
    }

    #pragma unroll 1
    for (int kk = 0; kk < 1024; kk += 32) {
        {
            int ao = arow * LDA + aq * 16;
            *(uint4*)&Ah[ao]     = aRh[0];
            *(uint4*)&Ah[ao + 8] = aRh[1];
            *(uint4*)&Al[ao]     = aRl[0];
            *(uint4*)&Al[ao + 8] = aRl[1];
            int bo = bk * LDB + bc;
            *(uint4*)&Bh[bo]     = bRh[0];
            *(uint4*)&Bh[bo + 8] = bRh[1];
            *(uint4*)&Bl[bo]     = bRl[0];
            *(uint4*)&Bl[bo + 8] = bRl[1];
        }
        __syncthreads();
        if (kk + 32 < 1024) {
            int k2 = kk + 32;
            #pragma unroll
            for (int i = 0; i < 2; i++) {
                aRh[i] = av ? *(const uint4*)(aH + k2 + 8 * i) : Z4;
                aRl[i] = av ? *(const uint4*)(aL + k2 + 8 * i) : Z4;
                bRh[i] = *(const uint4*)(bH + (size_t)k2 * NST + 8 * i);
                bRl[i] = *(const uint4*)(bL + (size_t)k2 * NST + 8 * i);
            }
        }
        #pragma unroll
        for (int ks = 0; ks < 2; ks++) {
            uint32_t ah[2][4], al2[2][4];
            #pragma unroll
            for (int t2 = 0; t2 < 2; t2++) {
                uint32_t off = (uint32_t)(((mb + t2 * 16 + fr) * LDA + ks * 16 + fc) * 2);
                ldsm4(sAh + off, ah[t2]);
                ldsm4(sAl + off, al2[t2]);
            }
            #pragma unroll
            for (int p = 0; p < 4; p++) {
                uint32_t bh[4], bl2[4];
                uint32_t off = (uint32_t)(((ks * 16 + fr) * LDB + nb + p * 16 + fc) * 2);
                ldsm4t(sBh + off, bh);
                ldsm4t(sBl + off, bl2);
                #pragma unroll
                for (int t2 = 0; t2 < 2; t2++) {
                    mma16816(acc[t2][2 * p],     ah[t2],  bh[0],  bh[1]);
                    mma16816(acc[t2][2 * p],     ah[t2],  bl2[0], bl2[1]);
                    mma16816(acc[t2][2 * p],     al2[t2], bh[0],  bh[1]);
                    mma16816(acc[t2][2 * p + 1], ah[t2],  bh[2],  bh[3]);
                    mma16816(acc[t2][2 * p + 1], ah[t2],  bl2[2], bl2[3]);
                    mma16816(acc[t2][2 * p + 1], al2[t2], bh[2],  bh[3]);
                }
            }
        }
        __syncthreads();
    }

    // ---- epilogue ----
    int r4 = lane >> 2, c2 = (lane & 3) * 2;
    if (G1) {
        const float* bp = bias + e * N_GU + n0;
        #pragma unroll
        for (int t2 = 0; t2 < 2; t2++) {
            int lr0 = mb + t2 * 16 + r4;
            int lr1 = lr0 + 8;
            bool v0 = lr0 < rows, v1 = lr1 < rows;
            size_t o0 = v0 ? (size_t)(rowStart + lr0) * INTER : 0;
            size_t o1 = v1 ? (size_t)(rowStart + lr1) * INTER : 0;
            #pragma unroll
            for (int p = 0; p < 4; p++)
                #pragma unroll
                for (int nt = 0; nt < 2; nt++) {
                    int nloc = nb + p * 16 + nt * 8 + c2;
                    float2 bb = *(const float2*)(bp + nloc);
                    float* c = acc[t2][2 * p + nt];
                    int ic = (n0 + nloc) >> 1;
                    if (v0) {
                        float v = swiglu(c[0] + bb.x, c[1] + bb.y);
                        uint16_t h, l; split1(v, h, l);
                        *(uint16_t*)&g_ih[o0 + ic] = h;
                        *(uint16_t*)&g_il[o0 + ic] = l;
                    }
                    if (v1) {
                        float v = swiglu(c[2] + bb.x, c[3] + bb.y);
                        uint16_t h, l; split1(v, h, l);
                        *(uint16_t*)&g_ih[o1 + ic] = h;
                        *(uint16_t*)&g_il[o1 + ic] = l;
                    }
                }
        }
    } else {
        // atomicAdd combine: exactly 2 contributions per output element;
        // fp32 add is commutative, so the result is order-independent (deterministic).
        const float* bp = bias + e * HIDDEN + n0;
        #pragma unroll
        for (int t2 = 0; t2 < 2; t2++) {
            int lr0 = mb + t2 * 16 + r4;
            int lr1 = lr0 + 8;
            bool v0 = lr0 < rows, v1 = lr1 < rows;
            int s0 = 0, s1 = 0; float w0 = 0.f, w1 = 0.f;
            if (v0) { int r = rowStart + lr0; s0 = g_perm[r]; w0 = g_w[r]; }
            if (v1) { int r = rowStart + lr1; s1 = g_perm[r]; w1 = g_w[r]; }
            float* outP0 = out + (size_t)(s0 >> 1) * HIDDEN + n0;
            float* outP1 = out + (size_t)(s1 >> 1) * HIDDEN + n0;
            #pragma unroll
            for (int p = 0; p < 4; p++)
                #pragma unroll
                for (int nt = 0; nt < 2; nt++) {
                    int nloc = nb + p * 16 + nt * 8 + c2;
                    float2 bb = *(const float2*)(bp + nloc);
                    float* c = acc[t2][2 * p + nt];
                    if (v0) {
                        atomicAdd(outP0 + nloc,     (c[0] + bb.x) * w0);
                        atomicAdd(outP0 + nloc + 1, (c[1] + bb.y) * w0);
                    }
                    if (v1) {
                        atomicAdd(outP1 + nloc,     (c[2] + bb.x) * w1);
                        atomicAdd(outP1 + nloc + 1, (c[3] + bb.y) * w1);
                    }
                }
        }
    }
}

// ---------------- launch ---------------------------------------------------
extern "C" void kernel_launch(void* const* d_in, const int* in_sizes, int n_in,
                              void* d_out, int out_size) {
    const float* hs   = (const float*)d_in[0];
    const int*   ridx = (const int*)  d_in[1];
    const float* rw   = (const float*)d_in[2];
    const float* gup  = (const float*)d_in[3];
    const float* gupb = (const float*)d_in[4];
    const float* dwn  = (const float*)d_in[5];
    const float* dwnb = (const float*)d_in[6];
    float* out = (float*)d_out;

    route_kernel<<<1, 256>>>(ridx, rw);

    // zero-init output (harness poisons it); capture-safe async memset
    cudaMemsetAsync(out, 0, (size_t)out_size * sizeof(float));

    // pre-split fp32 -> bf16 hi/lo (16 floats/thread, MLP=4)
    {
        int n16 = NUM_EXPERTS * HIDDEN * N_GU / 16;
        split_kernel<0><<<n16 / 256, 256>>>((const float4*)gup, n16);
    }
    {
        int n16 = NUM_EXPERTS * INTER * HIDDEN / 16;
        split_kernel<1><<<n16 / 256, 256>>>((const float4*)dwn, n16);
    }
    {
        int n16 = M_TOK * HIDDEN / 16;
        split_kernel<2><<<n16 / 256, 256>>>((const float4*)hs, n16);
    }

    dim3 grid1(MAX_TILES, N_GU / 128);    // (40, 16)
    gemm_kernel<true><<<grid1, 256>>>(gupb, out);
    dim3 grid2(MAX_TILES, HIDDEN / 128);  // (40, 8)
    gemm_kernel<false><<<grid2, 256>>>(dwnb, out);
}

// round 14
// speedup vs baseline: 1.0306x; 1.0163x over previous
#include <cuda_runtime.h>
#include <cuda_bf16.h>
#include <cstdint>

typedef __nv_bfloat16 bf16;

#define NUM_EXPERTS 8
#define HIDDEN     1024
#define INTER      1024
#define M_TOK      2048
#define NSLOT      4096
#define N_GU       2048
#define MAX_TILES  40

// ---------------- device scratch ----------------
__device__ int   g_perm[NSLOT];
__device__ float g_w[NSLOT];
__device__ int4  g_work[MAX_TILES];
__device__ bf16  g_w1h[(size_t)NUM_EXPERTS * HIDDEN * N_GU];
__device__ bf16  g_w1l[(size_t)NUM_EXPERTS * HIDDEN * N_GU];
__device__ bf16  g_w2h[(size_t)NUM_EXPERTS * INTER * HIDDEN];
__device__ bf16  g_w2l[(size_t)NUM_EXPERTS * INTER * HIDDEN];
__device__ bf16  g_xh[(size_t)M_TOK * HIDDEN];
__device__ bf16  g_xl[(size_t)M_TOK * HIDDEN];
__device__ bf16  g_ih[(size_t)NSLOT * INTER];
__device__ bf16  g_il[(size_t)NSLOT * INTER];

// ---------------- routing ----------------
__global__ void route_kernel(const int* __restrict__ ridx,
                             const float* __restrict__ rw) {
    __shared__ int cnt[NUM_EXPERTS];
    __shared__ int ofs[NUM_EXPERTS];
    __shared__ int cur[NUM_EXPERTS];
    int t = threadIdx.x;
    if (t < NUM_EXPERTS) cnt[t] = 0;
    __syncthreads();
    for (int s = t; s < NSLOT; s += blockDim.x)
        atomicAdd(&cnt[ridx[s]], 1);
    __syncthreads();
    if (t == 0) {
        int acc = 0;
        for (int e = 0; e < NUM_EXPERTS; e++) { ofs[e] = acc; cur[e] = acc; acc += cnt[e]; }
    }
    __syncthreads();
    for (int s = t; s < NSLOT; s += blockDim.x) {
        int e = ridx[s];
        int p = atomicAdd(&cur[e], 1);
        g_perm[p] = s;
        g_w[p]    = rw[(s >> 1) * NUM_EXPERTS + e];
    }
    if (t == 0) {
        int n = 0;
        for (int e = 0; e < NUM_EXPERTS; e++)
            for (int r = 0; r < cnt[e]; r += 128) {
                g_work[n] = make_int4(e, ofs[e] + r, min(128, cnt[e] - r), 0);
                n++;
            }
        for (; n < MAX_TILES; n++) g_work[n] = make_int4(0, 0, 0, 0);
    }
}

// ---------------- fp32 -> bf16 (hi, lo) split (R6-proven config) ----------------
__device__ __forceinline__ void split1(float x, uint16_t& h, uint16_t& l) {
    __nv_bfloat16 xh = __float2bfloat16_rn(x);
    h = __bfloat16_as_ushort(xh);
    l = __bfloat16_as_ushort(__float2bfloat16_rn(x - __bfloat162float(xh)));
}

// WHICH: 0 -> w1, 1 -> w2, 2 -> x. Destinations resolved IN DEVICE CODE.
// 4 floats per thread (max grid) — measured faster than wider variants.
template<int WHICH>
__global__ void split_kernel(const float4* __restrict__ in, int n4) {
    int i = blockIdx.x * blockDim.x + threadIdx.x;
    if (i >= n4) return;
    uint2* oh; uint2* ol;
    if (WHICH == 0)      { oh = (uint2*)g_w1h; ol = (uint2*)g_w1l; }
    else if (WHICH == 1) { oh = (uint2*)g_w2h; ol = (uint2*)g_w2l; }
    else                 { oh = (uint2*)g_xh;  ol = (uint2*)g_xl;  }
    float4 v = in[i];
    uint16_t h0, h1, h2, h3, l0, l1, l2, l3;
    split1(v.x, h0, l0); split1(v.y, h1, l1);
    split1(v.z, h2, l2); split1(v.w, h3, l3);
    oh[i] = make_uint2((uint32_t)h0 | ((uint32_t)h1 << 16), (uint32_t)h2 | ((uint32_t)h3 << 16));
    ol[i] = make_uint2((uint32_t)l0 | ((uint32_t)l1 << 16), (uint32_t)l2 | ((uint32_t)l3 << 16));
}

// ---------------- MMA helpers ----------------
__device__ __forceinline__ void ldsm4(uint32_t a, uint32_t* r) {
    asm volatile("ldmatrix.sync.aligned.m8n8.x4.shared.b16 {%0,%1,%2,%3},[%4];\n"
        : "=r"(r[0]), "=r"(r[1]), "=r"(r[2]), "=r"(r[3]) : "r"(a));
}
__device__ __forceinline__ void ldsm4t(uint32_t a, uint32_t* r) {
    asm volatile("ldmatrix.sync.aligned.m8n8.x4.trans.shared.b16 {%0,%1,%2,%3},[%4];\n"
        : "=r"(r[0]), "=r"(r[1]), "=r"(r[2]), "=r"(r[3]) : "r"(a));
}
__device__ __forceinline__ void mma16816(float* c, const uint32_t* a, uint32_t b0, uint32_t b1) {
    asm volatile("mma.sync.aligned.m16n8k16.row.col.f32.bf16.bf16.f32 "
        "{%0,%1,%2,%3},{%4,%5,%6,%7},{%8,%9},{%0,%1,%2,%3};\n"
        : "+f"(c[0]), "+f"(c[1]), "+f"(c[2]), "+f"(c[3])
        : "r"(a[0]), "r"(a[1]), "r"(a[2]), "r"(a[3]), "r"(b0), "r"(b1));
}
__device__ __forceinline__ float swiglu(float g, float u) {
    g = fminf(g, 7.0f);
    u = fminf(fmaxf(u, -7.0f), 7.0f);
    return (u + 1.0f) * (g / (1.0f + __expf(-1.702f * g)));
}

#define LDA 40     // A smem stride (bf16 elems): 32 data + 8 pad
#define LDB 136    // B smem stride: 128 data + 8 pad

// ---------------- grouped GEMM (G1: gate_up+SwiGLU, G2: down+atomic combine) -
// Mainloop is the PROVEN R6 structure (334.5us): static smem, register
// prefetch, two barriers per 32-K block. Do not reorder.
template<bool G1>
__global__ void __launch_bounds__(256, 1)
gemm_kernel(const float* __restrict__ bias, float* __restrict__ out) {
    int4 wk = g_work[blockIdx.x];
    int rows = wk.z;
    if (rows == 0) return;
    int e = wk.x, rowStart = wk.y;
    int n0 = blockIdx.y * 128;
    const int NST = G1 ? N_GU : HIDDEN;

    __shared__ uint16_t Ah[128 * LDA], Al[128 * LDA];
    __shared__ uint16_t Bh[32 * LDB],  Bl[32 * LDB];

    int tid = threadIdx.x, lane = tid & 31, wid = tid >> 5;

    // ---- global source pointers (pre-split bf16) ----
    int arow = tid >> 1, aq = tid & 1;          // A: 2 thr/row, 16 elems each
    bool av = arow < rows;
    int r_idx = rowStart + (av ? arow : 0);
    const bf16 *aH, *aL;
    if (G1) {
        int tok = g_perm[r_idx] >> 1;
        aH = g_xh + (size_t)tok * HIDDEN + aq * 16;
        aL = g_xl + (size_t)tok * HIDDEN + aq * 16;
    } else {
        aH = g_ih + (size_t)r_idx * INTER + aq * 16;
        aL = g_il + (size_t)r_idx * INTER + aq * 16;
    }
    int bk = tid >> 3, bc = (tid & 7) * 16;     // B: 8 thr/row, 16 elems each
    const bf16* bH = (G1 ? g_w1h : g_w2h) + (size_t)e * 1024 * NST + (size_t)bk * NST + n0 + bc;
    const bf16* bL = (G1 ? g_w1l : g_w2l) + (size_t)e * 1024 * NST + (size_t)bk * NST + n0 + bc;

    uint32_t sAh = (uint32_t)__cvta_generic_to_shared(Ah);
    uint32_t sAl = (uint32_t)__cvta_generic_to_shared(Al);
    uint32_t sBh = (uint32_t)__cvta_generic_to_shared(Bh);
    uint32_t sBl = (uint32_t)__cvta_generic_to_shared(Bl);

    int wm = wid & 3, wn = wid >> 2;
    int mb = wm * 32, nb = wn * 64;
    int fr = (lane & 7) + ((lane >> 3) & 1) * 8;
    int fc = (lane >> 4) * 8;

    float acc[2][8][4];
    #pragma unroll
    for (int a = 0; a < 2; a++)
        #pragma unroll
        for (int b = 0; b < 8; b++)
            #pragma unroll
            for (int c = 0; c < 4; c++) acc[a][b][c] = 0.f;

    const uint4 Z4 = make_uint4(0, 0, 0, 0);
    uint4 aRh[2], aRl[2], bRh[2], bRl[2];
    #pragma unroll
    for (int i = 0; i < 2; i++) {
        aRh[i] = av ? *(const uint4*)(aH + 8 * i) : Z4;
        aRl[i] = av ? *(const uint4*)(aL + 8 * i) : Z4;
        bRh[i] = *(const uint4*)(bH + 8 * i);
        bRl[i] = *(const uint4*)(bL + 8 * i);
    }

    #pragma unroll 1
    for (int kk = 0; kk < 1024; kk += 32) {
        {
            int ao = arow * LDA + aq * 16;
            *(uint4*)&Ah[ao]     = aRh[0];
            *(uint4*)&Ah[ao + 8] = aRh[1];
            *(uint4*)&Al[ao]     = aRl[0];
            *(uint4*)&Al[ao + 8] = aRl[1];
            int bo = bk * LDB + bc;
            *(uint4*)&Bh[bo]     = bRh[0];
            *(uint4*)&Bh[bo + 8] = bRh[1];
            *(uint4*)&Bl[bo]     = bRl[0];
            *(uint4*)&Bl[bo + 8] = bRl[1];
        }
        __syncthreads();
        if (kk + 32 < 1024) {
            int k2 = kk + 32;
            #pragma unroll
            for (int i = 0; i < 2; i++) {
                aRh[i] = av ? *(const uint4*)(aH + k2 + 8 * i) : Z4;
                aRl[i] = av ? *(const uint4*)(aL + k2 + 8 * i) : Z4;
                bRh[i] = *(const uint4*)(bH + (size_t)k2 * NST + 8 * i);
                bRl[i] = *(const uint4*)(bL + (size_t)k2 * NST + 8 * i);
            }
        }
        #pragma unroll
        for (int ks = 0; ks < 2; ks++) {
            uint32_t ah[2][4], al2[2][4];
            #pragma unroll
            for (int t2 = 0; t2 < 2; t2++) {
                uint32_t off = (uint32_t)(((mb + t2 * 16 + fr) * LDA + ks * 16 + fc) * 2);
                ldsm4(sAh + off, ah[t2]);
                ldsm4(sAl + off, al2[t2]);
            }
            #pragma unroll
            for (int p = 0; p < 4; p++) {
                uint32_t bh[4], bl2[4];
                uint32_t off = (uint32_t)(((ks * 16 + fr) * LDB + nb + p * 16 + fc) * 2);
                ldsm4t(sBh + off, bh);
                ldsm4t(sBl + off, bl2);
                #pragma unroll
                for (int t2 = 0; t2 < 2; t2++) {
                    mma16816(acc[t2][2 * p],     ah[t2],  bh[0],  bh[1]);
                    mma16816(acc[t2][2 * p],     ah[t2],  bl2[0], bl2[1]);
                    mma16816(acc[t2][2 * p],     al2[t2], bh[0],  bh[1]);
                    mma16816(acc[t2][2 * p + 1], ah[t2],  bh[2],  bh[3]);
                    mma16816(acc[t2][2 * p + 1], ah[t2],  bl2[2], bl2[3]);
                    mma16816(acc[t2][2 * p + 1], al2[t2], bh[2],  bh[3]);
                }
            }
        }
        __syncthreads();
    }

    // ---- epilogue ----
    int r4 = lane >> 2, c2 = (lane & 3) * 2;
    if (G1) {
        const float* bp = bias + e * N_GU + n0;
        #pragma unroll
        for (int t2 = 0; t2 < 2; t2++) {
            int lr0 = mb + t2 * 16 + r4;
            int lr1 = lr0 + 8;
            bool v0 = lr0 < rows, v1 = lr1 < rows;
            size_t o0 = v0 ? (size_t)(rowStart + lr0) * INTER : 0;
            size_t o1 = v1 ? (size_t)(rowStart + lr1) * INTER : 0;
            #pragma unroll
            for (int p = 0; p < 4; p++)
                #pragma unroll
                for (int nt = 0; nt < 2; nt++) {
                    int nloc = nb + p * 16 + nt * 8 + c2;
                    float2 bb = *(const float2*)(bp + nloc);
                    float* c = acc[t2][2 * p + nt];
                    int ic = (n0 + nloc) >> 1;
                    if (v0) {
                        float v = swiglu(c[0] + bb.x, c[1] + bb.y);
                        uint16_t h, l; split1(v, h, l);
                        *(uint16_t*)&g_ih[o0 + ic] = h;
                        *(uint16_t*)&g_il[o0 + ic] = l;
                    }
                    if (v1) {
                        float v = swiglu(c[2] + bb.x, c[3] + bb.y);
                        uint16_t h, l; split1(v, h, l);
                        *(uint16_t*)&g_ih[o1 + ic] = h;
                        *(uint16_t*)&g_il[o1 + ic] = l;
                    }
                }
        }
    } else {
        // atomicAdd combine: exactly 2 contributions per output element;
        // fp32 add is commutative -> order-independent -> deterministic.
        const float* bp = bias + e * HIDDEN + n0;
        #pragma unroll
        for (int t2 = 0; t2 < 2; t2++) {
            int lr0 = mb + t2 * 16 + r4;
            int lr1 = lr0 + 8;
            bool v0 = lr0 < rows, v1 = lr1 < rows;
            int s0 = 0, s1 = 0; float w0 = 0.f, w1 = 0.f;
            if (v0) { int r = rowStart + lr0; s0 = g_perm[r]; w0 = g_w[r]; }
            if (v1) { int r = rowStart + lr1; s1 = g_perm[r]; w1 = g_w[r]; }
            float* outP0 = out + (size_t)(s0 >> 1) * HIDDEN + n0;
            float* outP1 = out + (size_t)(s1 >> 1) * HIDDEN + n0;
            #pragma unroll
            for (int p = 0; p < 4; p++)
                #pragma unroll
                for (int nt = 0; nt < 2; nt++) {
                    int nloc = nb + p * 16 + nt * 8 + c2;
                    float2 bb = *(const float2*)(bp + nloc);
                    float* c = acc[t2][2 * p + nt];
                    if (v0) {
                        atomicAdd(outP0 + nloc,     (c[0] + bb.x) * w0);
                        atomicAdd(outP0 + nloc + 1, (c[1] + bb.y) * w0);
                    }
                    if (v1) {
                        atomicAdd(outP1 + nloc,     (c[2] + bb.x) * w1);
                        atomicAdd(outP1 + nloc + 1, (c[3] + bb.y) * w1);
                    }
                }
        }
    }
}

// ---------------- launch ---------------------------------------------------
extern "C" void kernel_launch(void* const* d_in, const int* in_sizes, int n_in,
                              void* d_out, int out_size) {
    const float* hs   = (const float*)d_in[0];
    const int*   ridx = (const int*)  d_in[1];
    const float* rw   = (const float*)d_in[2];
    const float* gup  = (const float*)d_in[3];
    const float* gupb = (const float*)d_in[4];
    const float* dwn  = (const float*)d_in[5];
    const float* dwnb = (const float*)d_in[6];
    float* out = (float*)d_out;

    route_kernel<<<1, 256>>>(ridx, rw);

    // zero-init output (harness poisons it); capture-safe async memset
    cudaMemsetAsync(out, 0, (size_t)out_size * sizeof(float));

    // pre-split fp32 -> bf16 hi/lo (R6-proven 4-floats/thread config)
    {
        int n4 = NUM_EXPERTS * HIDDEN * N_GU / 4;
        split_kernel<0><<<n4 / 256, 256>>>((const float4*)gup, n4);
    }
    {
        int n4 = NUM_EXPERTS * INTER * HIDDEN / 4;
        split_kernel<1><<<n4 / 256, 256>>>((const float4*)dwn, n4);
    }
    {
        int n4 = M_TOK * HIDDEN / 4;
        split_kernel<2><<<n4 / 256, 256>>>((const float4*)hs, n4);
    }

    dim3 grid1(MAX_TILES, N_GU / 128);    // (40, 16)
    gemm_kernel<true><<<grid1, 256>>>(gupb, out);
    dim3 grid2(MAX_TILES, HIDDEN / 128);  // (40, 8)
    gemm_kernel<false><<<grid2, 256>>>(dwnb, out);
}